// round 1
// baseline (speedup 1.0000x reference)
#include <cuda_runtime.h>
#include <cstddef>

// LightGCN on a bipartite graph, fp32.
// Pipeline per launch (all graph-capturable, no allocations):
//   1. zero degree counters (memsetAsync on __device__ globals)
//   2. degree histogram (atomicAdd)
//   3. per-edge symmetric-normalization weight w[e]
//   4. init x0 = concat(user_table, item_table); acc = x0
//   5. 3x { zero x_next; scatter x_next[r] += w*x_cur[c] over 3.2M directed
//           edges with red.global.add.v4.f32; acc += x_next; swap }
//   6. batched scoring: pos/neg dot products of acc/4, plus L2 reg reduction.

#define NU_MAX 100000
#define NI_MAX 50000
#define N_MAX  (NU_MAX + NI_MAX)
#define E_MAX  1600000
#define EMB_D  64

// Scratch (static device globals; allocation-free per harness rules).
__device__ float g_deg_u[NU_MAX];
__device__ float g_deg_i[NI_MAX];
__device__ float g_w[E_MAX];
__device__ float g_xa[(size_t)N_MAX * EMB_D];
__device__ float g_xb[(size_t)N_MAX * EMB_D];
__device__ float g_acc[(size_t)N_MAX * EMB_D];

// ---------------------------------------------------------------------------
// 2. degree histogram
__global__ void deg_kernel(const int* __restrict__ eu, const int* __restrict__ ei, int E) {
    int e = blockIdx.x * blockDim.x + threadIdx.x;
    if (e < E) {
        atomicAdd(&g_deg_u[eu[e]], 1.0f);
        atomicAdd(&g_deg_i[ei[e]], 1.0f);
    }
}

// 3. w[e] = rsqrt(max(deg_u * deg_i, 1))
__global__ void w_kernel(const int* __restrict__ eu, const int* __restrict__ ei, int E) {
    int e = blockIdx.x * blockDim.x + threadIdx.x;
    if (e < E) {
        float du = g_deg_u[eu[e]];
        float di = g_deg_i[ei[e]];
        g_w[e] = rsqrtf(fmaxf(du * di, 1.0f));
    }
}

// 4. x0 = concat(tables); acc = x0   (float4 elements)
__global__ void init_kernel(const float4* __restrict__ ut, const float4* __restrict__ it,
                            int nu4, int ntot4) {
    int i = blockIdx.x * blockDim.x + threadIdx.x;
    if (i < ntot4) {
        float4 v = (i < nu4) ? ut[i] : it[i - nu4];
        reinterpret_cast<float4*>(g_xa)[i] = v;
        reinterpret_cast<float4*>(g_acc)[i] = v;
    }
}

// 5a. scatter: one thread per (directed edge, float4 chunk). 16 threads/edge.
__global__ void scatter_kernel(const float* __restrict__ xs, float* __restrict__ xd,
                               const int* __restrict__ eu, const int* __restrict__ ei,
                               int E, int n_users) {
    int idx = blockIdx.x * blockDim.x + threadIdx.x;
    int de  = idx >> 4;        // directed edge id
    int sub = idx & 15;        // float4 chunk within the 64-float row
    int D2 = 2 * E;
    if (de >= D2) return;
    int e, r, c;
    if (de < E) { e = de;     r = eu[e];           c = n_users + ei[e]; }
    else        { e = de - E; r = n_users + ei[e]; c = eu[e];           }
    float w = __ldg(&g_w[e]);
    float4 v = __ldg(reinterpret_cast<const float4*>(xs + (size_t)c * EMB_D) + sub);
    float4 t = make_float4(v.x * w, v.y * w, v.z * w, v.w * w);
    float* p = xd + (size_t)r * EMB_D + (sub << 2);
    // Vector reduction (sm_90+): one LTS op per 16B instead of 4 scalar atomics.
    asm volatile("red.global.add.v4.f32 [%0], {%1, %2, %3, %4};"
                 :: "l"(p), "f"(t.x), "f"(t.y), "f"(t.z), "f"(t.w)
                 : "memory");
}

// 5b. acc += x_next
__global__ void axpy_kernel(const float4* __restrict__ src, float4* __restrict__ dst, int n4) {
    int i = blockIdx.x * blockDim.x + threadIdx.x;
    if (i < n4) {
        float4 a = dst[i];
        float4 b = src[i];
        a.x += b.x; a.y += b.y; a.z += b.z; a.w += b.w;
        dst[i] = a;
    }
}

// 6. scoring: one warp per batch element. final emb = acc/4 -> dot/16.
__global__ void score_kernel(const float* __restrict__ ut, const float* __restrict__ it,
                             const int* __restrict__ users, const int* __restrict__ pos,
                             const int* __restrict__ neg,
                             float* __restrict__ out, int B, int n_users) {
    int warp = (blockIdx.x * blockDim.x + threadIdx.x) >> 5;
    int lane = threadIdx.x & 31;
    if (warp >= B) return;
    int u = users[warp];
    int p = pos[warp];
    int n = neg[warp];

    const float2* au = reinterpret_cast<const float2*>(g_acc + (size_t)u * EMB_D);
    const float2* ap = reinterpret_cast<const float2*>(g_acc + (size_t)(n_users + p) * EMB_D);
    const float2* an = reinterpret_cast<const float2*>(g_acc + (size_t)(n_users + n) * EMB_D);
    float2 vu = au[lane], vp = ap[lane], vn = an[lane];
    float ps = vu.x * vp.x + vu.y * vp.y;
    float ns = vu.x * vn.x + vu.y * vn.y;

    const float2* tu = reinterpret_cast<const float2*>(ut + (size_t)u * EMB_D);
    const float2* tp = reinterpret_cast<const float2*>(it + (size_t)p * EMB_D);
    const float2* tn = reinterpret_cast<const float2*>(it + (size_t)n * EMB_D);
    float2 a = tu[lane], b = tp[lane], c = tn[lane];
    float rg = a.x * a.x + a.y * a.y + b.x * b.x + b.y * b.y + c.x * c.x + c.y * c.y;

    #pragma unroll
    for (int o = 16; o > 0; o >>= 1) {
        ps += __shfl_down_sync(0xFFFFFFFFu, ps, o);
        ns += __shfl_down_sync(0xFFFFFFFFu, ns, o);
        rg += __shfl_down_sync(0xFFFFFFFFu, rg, o);
    }
    if (lane == 0) {
        out[warp]     = ps * (1.0f / 16.0f);   // (acc/4).(acc/4)
        out[B + warp] = ns * (1.0f / 16.0f);
        atomicAdd(&out[2 * B], rg * (1e-4f / (float)B));
    }
}

// ---------------------------------------------------------------------------
extern "C" void kernel_launch(void* const* d_in, const int* in_sizes, int n_in,
                              void* d_out, int out_size) {
    const float* ut    = (const float*)d_in[0];
    const float* it    = (const float*)d_in[1];
    const int*   eu    = (const int*)d_in[2];
    const int*   ei    = (const int*)d_in[3];
    const int*   users = (const int*)d_in[4];
    const int*   pos   = (const int*)d_in[5];
    const int*   neg   = (const int*)d_in[6];
    float*       out   = (float*)d_out;

    const int n_users = in_sizes[0] / EMB_D;
    const int n_items = in_sizes[1] / EMB_D;
    const int E       = in_sizes[2];
    const int B       = in_sizes[4];
    const int N       = n_users + n_items;
    const int n4      = N * EMB_D / 4;

    void *p_deg_u, *p_deg_i, *p_xa, *p_xb, *p_acc;
    cudaGetSymbolAddress(&p_deg_u, g_deg_u);
    cudaGetSymbolAddress(&p_deg_i, g_deg_i);
    cudaGetSymbolAddress(&p_xa, g_xa);
    cudaGetSymbolAddress(&p_xb, g_xb);
    cudaGetSymbolAddress(&p_acc, g_acc);

    const int T = 256;

    cudaMemsetAsync(p_deg_u, 0, (size_t)n_users * sizeof(float), 0);
    cudaMemsetAsync(p_deg_i, 0, (size_t)n_items * sizeof(float), 0);
    deg_kernel<<<(E + T - 1) / T, T>>>(eu, ei, E);
    w_kernel<<<(E + T - 1) / T, T>>>(eu, ei, E);

    init_kernel<<<(n4 + T - 1) / T, T>>>((const float4*)ut, (const float4*)it,
                                         n_users * EMB_D / 4, n4);

    float* xa = (float*)p_xa;
    float* xb = (float*)p_xb;
    const long long scat_threads = (long long)2 * E * 16;
    const int scat_blocks = (int)((scat_threads + T - 1) / T);

    for (int layer = 0; layer < 3; ++layer) {
        cudaMemsetAsync(xb, 0, (size_t)N * EMB_D * sizeof(float), 0);
        scatter_kernel<<<scat_blocks, T>>>(xa, xb, eu, ei, E, n_users);
        axpy_kernel<<<(n4 + T - 1) / T, T>>>((const float4*)xb, (float4*)p_acc, n4);
        float* t = xa; xa = xb; xb = t;
    }

    cudaMemsetAsync(out + 2 * B, 0, sizeof(float), 0);
    score_kernel<<<(B * 32 + T - 1) / T, T>>>(ut, it, users, pos, neg, out, B, n_users);
}

// round 2
// speedup vs baseline: 1.7670x; 1.7670x over previous
#include <cuda_runtime.h>
#include <cstddef>

// LightGCN, fp32, CSR-gather formulation (no mainloop atomics).
// Per launch:
//   1. int degree histogram
//   2. per-edge symmetric-normalization weight w[e]
//   3. exclusive scan of degrees -> CSR offsets (3 small kernels)
//   4. fill packed adjacency (src, w) with atomic cursors
//   5. init x0 = concat(tables); acc = x0
//   6. 3x fused gather: x_next[r] = sum_j w_j * x_cur[c_j]; acc += x_next
//   7. batched scoring + L2 reg

#define NU_MAX 100000
#define NI_MAX 50000
#define N_MAX  (NU_MAX + NI_MAX)
#define E_MAX  1600000
#define EMB_D  64
#define SCAN_B 1024

// Scratch (static device globals; allocation-free per harness rules).
__device__ int   g_degi_u[NU_MAX];
__device__ int   g_degi_i[NI_MAX];
__device__ float g_w[E_MAX];
__device__ int   g_off[N_MAX + 1];
__device__ int   g_cur[N_MAX];
__device__ int   g_bsum[(N_MAX + SCAN_B) / SCAN_B + 2];
__device__ int2  g_adj[(size_t)2 * E_MAX];
__device__ float g_xa[(size_t)N_MAX * EMB_D];
__device__ float g_xb[(size_t)N_MAX * EMB_D];
__device__ float g_acc[(size_t)N_MAX * EMB_D];

// ---------------------------------------------------------------------------
// 1. degree histogram (int)
__global__ void deg_kernel(const int* __restrict__ eu, const int* __restrict__ ei, int E) {
    int e = blockIdx.x * blockDim.x + threadIdx.x;
    if (e < E) {
        atomicAdd(&g_degi_u[eu[e]], 1);
        atomicAdd(&g_degi_i[ei[e]], 1);
    }
}

// 2. w[e] = rsqrt(max(deg_u * deg_i, 1))
__global__ void w_kernel(const int* __restrict__ eu, const int* __restrict__ ei, int E) {
    int e = blockIdx.x * blockDim.x + threadIdx.x;
    if (e < E) {
        float du = (float)g_degi_u[eu[e]];
        float di = (float)g_degi_i[ei[e]];
        g_w[e] = rsqrtf(fmaxf(du * di, 1.0f));
    }
}

// degree of stacked node i (index N treated as 0 so scan yields off[N] = 2E)
__device__ __forceinline__ int node_deg(int i, int nu, int N) {
    if (i < nu) return g_degi_u[i];
    if (i < N)  return g_degi_i[i - nu];
    return 0;
}

// 3a. per-block exclusive scan over n = N+1 degree entries
__global__ void scan1_kernel(int n, int nu, int N) {
    __shared__ int sh[SCAN_B];
    int tid = threadIdx.x;
    int i = blockIdx.x * SCAN_B + tid;
    int v = (i < n) ? node_deg(i, nu, N) : 0;
    sh[tid] = v;
    __syncthreads();
    #pragma unroll
    for (int o = 1; o < SCAN_B; o <<= 1) {
        int t = (tid >= o) ? sh[tid - o] : 0;
        __syncthreads();
        sh[tid] += t;
        __syncthreads();
    }
    if (i < n) g_off[i] = sh[tid] - v;      // exclusive within block
    if (tid == SCAN_B - 1) g_bsum[blockIdx.x] = sh[tid];
}

// 3b. exclusive scan of block sums (single block; nb <= 1024)
__global__ void scan2_kernel(int nb) {
    __shared__ int sh[SCAN_B];
    int tid = threadIdx.x;
    int v = (tid < nb) ? g_bsum[tid] : 0;
    sh[tid] = v;
    __syncthreads();
    #pragma unroll
    for (int o = 1; o < SCAN_B; o <<= 1) {
        int t = (tid >= o) ? sh[tid - o] : 0;
        __syncthreads();
        sh[tid] += t;
        __syncthreads();
    }
    if (tid < nb) g_bsum[tid] = sh[tid] - v; // exclusive
}

// 3c. add scanned block offsets
__global__ void scan3_kernel(int n) {
    int i = blockIdx.x * SCAN_B + threadIdx.x;
    if (i < n) g_off[i] += g_bsum[blockIdx.x];
}

// 4. fill packed adjacency: for each undirected edge, two directed entries
__global__ void fill_kernel(const int* __restrict__ eu, const int* __restrict__ ei,
                            int E, int nu) {
    int e = blockIdx.x * blockDim.x + threadIdx.x;
    if (e >= E) return;
    int u = eu[e];
    int it = ei[e];
    int wb = __float_as_int(g_w[e]);
    int p1 = atomicAdd(&g_cur[u], 1);
    g_adj[(size_t)g_off[u] + p1] = make_int2(nu + it, wb);
    int r2 = nu + it;
    int p2 = atomicAdd(&g_cur[r2], 1);
    g_adj[(size_t)g_off[r2] + p2] = make_int2(u, wb);
}

// 5. x0 = concat(tables); acc = x0
__global__ void init_kernel(const float4* __restrict__ ut, const float4* __restrict__ it,
                            int nu4, int ntot4) {
    int i = blockIdx.x * blockDim.x + threadIdx.x;
    if (i < ntot4) {
        float4 v = (i < nu4) ? ut[i] : it[i - nu4];
        reinterpret_cast<float4*>(g_xa)[i] = v;
        reinterpret_cast<float4*>(g_acc)[i] = v;
    }
}

// 6. fused gather: one warp per destination node, float2 per lane.
__global__ void gather_kernel(const float* __restrict__ xs, float* __restrict__ xd,
                              float* __restrict__ acc, int N) {
    int warp = (blockIdx.x * blockDim.x + threadIdx.x) >> 5;
    int lane = threadIdx.x & 31;
    if (warp >= N) return;
    int beg = g_off[warp];
    int end = g_off[warp + 1];
    float sx = 0.0f, sy = 0.0f;
    int j = beg;
    for (; j + 3 < end; j += 4) {
        int2 a0 = __ldg(&g_adj[j]);
        int2 a1 = __ldg(&g_adj[j + 1]);
        int2 a2 = __ldg(&g_adj[j + 2]);
        int2 a3 = __ldg(&g_adj[j + 3]);
        float2 v0 = __ldg(reinterpret_cast<const float2*>(xs + (size_t)a0.x * EMB_D) + lane);
        float2 v1 = __ldg(reinterpret_cast<const float2*>(xs + (size_t)a1.x * EMB_D) + lane);
        float2 v2 = __ldg(reinterpret_cast<const float2*>(xs + (size_t)a2.x * EMB_D) + lane);
        float2 v3 = __ldg(reinterpret_cast<const float2*>(xs + (size_t)a3.x * EMB_D) + lane);
        float w0 = __int_as_float(a0.y), w1 = __int_as_float(a1.y);
        float w2 = __int_as_float(a2.y), w3 = __int_as_float(a3.y);
        sx += w0 * v0.x + w1 * v1.x + w2 * v2.x + w3 * v3.x;
        sy += w0 * v0.y + w1 * v1.y + w2 * v2.y + w3 * v3.y;
    }
    for (; j < end; ++j) {
        int2 a = __ldg(&g_adj[j]);
        float2 v = __ldg(reinterpret_cast<const float2*>(xs + (size_t)a.x * EMB_D) + lane);
        float w = __int_as_float(a.y);
        sx += w * v.x;
        sy += w * v.y;
    }
    float2* pd = reinterpret_cast<float2*>(xd + (size_t)warp * EMB_D) + lane;
    *pd = make_float2(sx, sy);
    float2* pa = reinterpret_cast<float2*>(acc + (size_t)warp * EMB_D) + lane;
    float2 av = *pa;
    av.x += sx;
    av.y += sy;
    *pa = av;
}

// 7. scoring: one warp per batch element. final emb = acc/4 -> dot/16.
__global__ void score_kernel(const float* __restrict__ ut, const float* __restrict__ it,
                             const int* __restrict__ users, const int* __restrict__ pos,
                             const int* __restrict__ neg,
                             float* __restrict__ out, int B, int n_users) {
    int warp = (blockIdx.x * blockDim.x + threadIdx.x) >> 5;
    int lane = threadIdx.x & 31;
    if (warp >= B) return;
    int u = users[warp];
    int p = pos[warp];
    int n = neg[warp];

    const float2* au = reinterpret_cast<const float2*>(g_acc + (size_t)u * EMB_D);
    const float2* ap = reinterpret_cast<const float2*>(g_acc + (size_t)(n_users + p) * EMB_D);
    const float2* an = reinterpret_cast<const float2*>(g_acc + (size_t)(n_users + n) * EMB_D);
    float2 vu = au[lane], vp = ap[lane], vn = an[lane];
    float ps = vu.x * vp.x + vu.y * vp.y;
    float ns = vu.x * vn.x + vu.y * vn.y;

    const float2* tu = reinterpret_cast<const float2*>(ut + (size_t)u * EMB_D);
    const float2* tp = reinterpret_cast<const float2*>(it + (size_t)p * EMB_D);
    const float2* tn = reinterpret_cast<const float2*>(it + (size_t)n * EMB_D);
    float2 a = tu[lane], b = tp[lane], c = tn[lane];
    float rg = a.x * a.x + a.y * a.y + b.x * b.x + b.y * b.y + c.x * c.x + c.y * c.y;

    #pragma unroll
    for (int o = 16; o > 0; o >>= 1) {
        ps += __shfl_down_sync(0xFFFFFFFFu, ps, o);
        ns += __shfl_down_sync(0xFFFFFFFFu, ns, o);
        rg += __shfl_down_sync(0xFFFFFFFFu, rg, o);
    }
    if (lane == 0) {
        out[warp]     = ps * (1.0f / 16.0f);   // (acc/4).(acc/4)
        out[B + warp] = ns * (1.0f / 16.0f);
        atomicAdd(&out[2 * B], rg * (1e-4f / (float)B));
    }
}

// ---------------------------------------------------------------------------
extern "C" void kernel_launch(void* const* d_in, const int* in_sizes, int n_in,
                              void* d_out, int out_size) {
    const float* ut    = (const float*)d_in[0];
    const float* it    = (const float*)d_in[1];
    const int*   eu    = (const int*)d_in[2];
    const int*   ei    = (const int*)d_in[3];
    const int*   users = (const int*)d_in[4];
    const int*   pos   = (const int*)d_in[5];
    const int*   neg   = (const int*)d_in[6];
    float*       out   = (float*)d_out;

    const int n_users = in_sizes[0] / EMB_D;
    const int n_items = in_sizes[1] / EMB_D;
    const int E       = in_sizes[2];
    const int B       = in_sizes[4];
    const int N       = n_users + n_items;
    const int n4      = N * EMB_D / 4;

    void *p_degu, *p_degi, *p_cur, *p_xa, *p_xb, *p_acc;
    cudaGetSymbolAddress(&p_degu, g_degi_u);
    cudaGetSymbolAddress(&p_degi, g_degi_i);
    cudaGetSymbolAddress(&p_cur, g_cur);
    cudaGetSymbolAddress(&p_xa, g_xa);
    cudaGetSymbolAddress(&p_xb, g_xb);
    cudaGetSymbolAddress(&p_acc, g_acc);

    const int T = 256;

    // 1-2: degrees + weights
    cudaMemsetAsync(p_degu, 0, (size_t)n_users * sizeof(int), 0);
    cudaMemsetAsync(p_degi, 0, (size_t)n_items * sizeof(int), 0);
    deg_kernel<<<(E + T - 1) / T, T>>>(eu, ei, E);
    w_kernel<<<(E + T - 1) / T, T>>>(eu, ei, E);

    // 3: exclusive scan over N+1 degree entries -> g_off (off[N] = 2E)
    const int n_scan = N + 1;
    const int nb = (n_scan + SCAN_B - 1) / SCAN_B;
    scan1_kernel<<<nb, SCAN_B>>>(n_scan, n_users, N);
    scan2_kernel<<<1, SCAN_B>>>(nb);
    scan3_kernel<<<nb, SCAN_B>>>(n_scan);

    // 4: adjacency fill
    cudaMemsetAsync(p_cur, 0, (size_t)N * sizeof(int), 0);
    fill_kernel<<<(E + T - 1) / T, T>>>(eu, ei, E, n_users);

    // 5: init
    init_kernel<<<(n4 + T - 1) / T, T>>>((const float4*)ut, (const float4*)it,
                                         n_users * EMB_D / 4, n4);

    // 6: 3 fused gather layers
    float* xa = (float*)p_xa;
    float* xb = (float*)p_xb;
    const int gwarps_per_block = T / 32;
    const int gblocks = (N + gwarps_per_block - 1) / gwarps_per_block;
    for (int layer = 0; layer < 3; ++layer) {
        gather_kernel<<<gblocks, T>>>(xa, xb, (float*)p_acc, N);
        float* t = xa; xa = xb; xb = t;
    }

    // 7: scoring
    cudaMemsetAsync(out + 2 * B, 0, sizeof(float), 0);
    score_kernel<<<(B * 32 + T - 1) / T, T>>>(ut, it, users, pos, neg, out, B, n_users);
}

// round 3
// speedup vs baseline: 2.3788x; 1.3463x over previous
#include <cuda_runtime.h>
#include <cstddef>

// LightGCN, fp32, CSR-gather, batch-sparse final layer.
// Per launch:
//   1. int degree histogram
//   2. per-edge symmetric-normalization weight w[e]
//   3. exclusive scan of degrees -> CSR offsets
//   4. fill packed adjacency (src, w) with atomic cursors
//   5. x1 = gather(tables); x2 = gather(x1)          (full graph, 2 layers)
//   6. fe[idx] = 0.25*(x0 + x1 + x2 + gather(x2))     (batch rows only, 12k)
//   7. scoring from fe + L2 reg from tables

#define NU_MAX 100000
#define NI_MAX 50000
#define N_MAX  (NU_MAX + NI_MAX)
#define E_MAX  1600000
#define B_MAX  4096
#define EMB_D  64
#define SCAN_B 1024

__device__ int   g_degi_u[NU_MAX];
__device__ int   g_degi_i[NI_MAX];
__device__ float g_w[E_MAX];
__device__ int   g_off[N_MAX + 1];
__device__ int   g_cur[N_MAX];
__device__ int   g_bsum[(N_MAX + SCAN_B) / SCAN_B + 2];
__device__ int2  g_adj[(size_t)2 * E_MAX];
__device__ float g_x1[(size_t)N_MAX * EMB_D];
__device__ float g_x2[(size_t)N_MAX * EMB_D];
__device__ float g_fe[(size_t)3 * B_MAX * EMB_D];

// ---------------------------------------------------------------------------
__global__ void deg_kernel(const int* __restrict__ eu, const int* __restrict__ ei, int E) {
    int e = blockIdx.x * blockDim.x + threadIdx.x;
    if (e < E) {
        atomicAdd(&g_degi_u[eu[e]], 1);
        atomicAdd(&g_degi_i[ei[e]], 1);
    }
}

__global__ void w_kernel(const int* __restrict__ eu, const int* __restrict__ ei, int E) {
    int e = blockIdx.x * blockDim.x + threadIdx.x;
    if (e < E) {
        float du = (float)g_degi_u[eu[e]];
        float di = (float)g_degi_i[ei[e]];
        g_w[e] = rsqrtf(fmaxf(du * di, 1.0f));
    }
}

__device__ __forceinline__ int node_deg(int i, int nu, int N) {
    if (i < nu) return g_degi_u[i];
    if (i < N)  return g_degi_i[i - nu];
    return 0;
}

__global__ void scan1_kernel(int n, int nu, int N) {
    __shared__ int sh[SCAN_B];
    int tid = threadIdx.x;
    int i = blockIdx.x * SCAN_B + tid;
    int v = (i < n) ? node_deg(i, nu, N) : 0;
    sh[tid] = v;
    __syncthreads();
    #pragma unroll
    for (int o = 1; o < SCAN_B; o <<= 1) {
        int t = (tid >= o) ? sh[tid - o] : 0;
        __syncthreads();
        sh[tid] += t;
        __syncthreads();
    }
    if (i < n) g_off[i] = sh[tid] - v;
    if (tid == SCAN_B - 1) g_bsum[blockIdx.x] = sh[tid];
}

__global__ void scan2_kernel(int nb) {
    __shared__ int sh[SCAN_B];
    int tid = threadIdx.x;
    int v = (tid < nb) ? g_bsum[tid] : 0;
    sh[tid] = v;
    __syncthreads();
    #pragma unroll
    for (int o = 1; o < SCAN_B; o <<= 1) {
        int t = (tid >= o) ? sh[tid - o] : 0;
        __syncthreads();
        sh[tid] += t;
        __syncthreads();
    }
    if (tid < nb) g_bsum[tid] = sh[tid] - v;
}

__global__ void scan3_kernel(int n) {
    int i = blockIdx.x * SCAN_B + threadIdx.x;
    if (i < n) g_off[i] += g_bsum[blockIdx.x];
}

__global__ void fill_kernel(const int* __restrict__ eu, const int* __restrict__ ei,
                            int E, int nu) {
    int e = blockIdx.x * blockDim.x + threadIdx.x;
    if (e >= E) return;
    int u = eu[e];
    int it = ei[e];
    int wb = __float_as_int(g_w[e]);
    int p1 = atomicAdd(&g_cur[u], 1);
    g_adj[(size_t)g_off[u] + p1] = make_int2(nu + it, wb);
    int r2 = nu + it;
    int p2 = atomicAdd(&g_cur[r2], 1);
    g_adj[(size_t)g_off[r2] + p2] = make_int2(u, wb);
}

// gathered row of x (float2 per lane) summed over neighbors of node `node`.
// Source row selected via fsrc(c): either stacked tables or a dense buffer.
struct StackedSrc {
    const float* ut; const float* it; int nu;
    __device__ __forceinline__ const float2* row(int c) const {
        const float* base = (c < nu) ? (ut + (size_t)c * EMB_D)
                                     : (it + (size_t)(c - nu) * EMB_D);
        return reinterpret_cast<const float2*>(base);
    }
};
struct DenseSrc {
    const float* x;
    __device__ __forceinline__ const float2* row(int c) const {
        return reinterpret_cast<const float2*>(x + (size_t)c * EMB_D);
    }
};

template <typename Src>
__device__ __forceinline__ float2 gather_row(const Src& src, int node, int lane) {
    int beg = g_off[node];
    int end = g_off[node + 1];
    float sx = 0.0f, sy = 0.0f;
    int j = beg;
    for (; j + 3 < end; j += 4) {
        int2 a0 = __ldg(&g_adj[j]);
        int2 a1 = __ldg(&g_adj[j + 1]);
        int2 a2 = __ldg(&g_adj[j + 2]);
        int2 a3 = __ldg(&g_adj[j + 3]);
        float2 v0 = __ldg(src.row(a0.x) + lane);
        float2 v1 = __ldg(src.row(a1.x) + lane);
        float2 v2 = __ldg(src.row(a2.x) + lane);
        float2 v3 = __ldg(src.row(a3.x) + lane);
        float w0 = __int_as_float(a0.y), w1 = __int_as_float(a1.y);
        float w2 = __int_as_float(a2.y), w3 = __int_as_float(a3.y);
        sx += w0 * v0.x + w1 * v1.x + w2 * v2.x + w3 * v3.x;
        sy += w0 * v0.y + w1 * v1.y + w2 * v2.y + w3 * v3.y;
    }
    for (; j < end; ++j) {
        int2 a = __ldg(&g_adj[j]);
        float2 v = __ldg(src.row(a.x) + lane);
        float w = __int_as_float(a.y);
        sx += w * v.x;
        sy += w * v.y;
    }
    return make_float2(sx, sy);
}

// 5a. x1 = gather(tables)  — one warp per node
__global__ void gather1_kernel(const float* __restrict__ ut, const float* __restrict__ it,
                               int nu, int N) {
    int warp = (blockIdx.x * blockDim.x + threadIdx.x) >> 5;
    int lane = threadIdx.x & 31;
    if (warp >= N) return;
    StackedSrc src{ut, it, nu};
    float2 s = gather_row(src, warp, lane);
    reinterpret_cast<float2*>(g_x1 + (size_t)warp * EMB_D)[lane] = s;
}

// 5b. x2 = gather(x1)
__global__ void gather2_kernel(int N) {
    int warp = (blockIdx.x * blockDim.x + threadIdx.x) >> 5;
    int lane = threadIdx.x & 31;
    if (warp >= N) return;
    DenseSrc src{g_x1};
    float2 s = gather_row(src, warp, lane);
    reinterpret_cast<float2*>(g_x2 + (size_t)warp * EMB_D)[lane] = s;
}

// 6. fe[idx] = 0.25*(x0 + x1 + x2 + gather(x2))  for the 3B batch rows
__global__ void final_kernel(const float* __restrict__ ut, const float* __restrict__ it,
                             const int* __restrict__ users, const int* __restrict__ pos,
                             const int* __restrict__ neg, int B, int nu) {
    int idx  = (blockIdx.x * blockDim.x + threadIdx.x) >> 5;
    int lane = threadIdx.x & 31;
    if (idx >= 3 * B) return;
    int node;
    if (idx < B)            node = users[idx];
    else if (idx < 2 * B)   node = nu + pos[idx - B];
    else                    node = nu + neg[idx - 2 * B];

    DenseSrc src{g_x2};
    float2 x3 = gather_row(src, node, lane);

    const float* base0 = (node < nu) ? (ut + (size_t)node * EMB_D)
                                     : (it + (size_t)(node - nu) * EMB_D);
    float2 x0 = reinterpret_cast<const float2*>(base0)[lane];
    float2 x1 = reinterpret_cast<const float2*>(g_x1 + (size_t)node * EMB_D)[lane];
    float2 x2 = reinterpret_cast<const float2*>(g_x2 + (size_t)node * EMB_D)[lane];
    float2 f = make_float2(0.25f * (x0.x + x1.x + x2.x + x3.x),
                           0.25f * (x0.y + x1.y + x2.y + x3.y));
    reinterpret_cast<float2*>(g_fe + (size_t)idx * EMB_D)[lane] = f;
}

// 7. scoring: one warp per batch element.
__global__ void score_kernel(const float* __restrict__ ut, const float* __restrict__ it,
                             const int* __restrict__ users, const int* __restrict__ pos,
                             const int* __restrict__ neg,
                             float* __restrict__ out, int B) {
    int warp = (blockIdx.x * blockDim.x + threadIdx.x) >> 5;
    int lane = threadIdx.x & 31;
    if (warp >= B) return;

    float2 vu = reinterpret_cast<const float2*>(g_fe + (size_t)warp * EMB_D)[lane];
    float2 vp = reinterpret_cast<const float2*>(g_fe + (size_t)(B + warp) * EMB_D)[lane];
    float2 vn = reinterpret_cast<const float2*>(g_fe + (size_t)(2 * B + warp) * EMB_D)[lane];
    float ps = vu.x * vp.x + vu.y * vp.y;
    float ns = vu.x * vn.x + vu.y * vn.y;

    int u = users[warp];
    int p = pos[warp];
    int n = neg[warp];
    float2 a = reinterpret_cast<const float2*>(ut + (size_t)u * EMB_D)[lane];
    float2 b = reinterpret_cast<const float2*>(it + (size_t)p * EMB_D)[lane];
    float2 c = reinterpret_cast<const float2*>(it + (size_t)n * EMB_D)[lane];
    float rg = a.x * a.x + a.y * a.y + b.x * b.x + b.y * b.y + c.x * c.x + c.y * c.y;

    #pragma unroll
    for (int o = 16; o > 0; o >>= 1) {
        ps += __shfl_down_sync(0xFFFFFFFFu, ps, o);
        ns += __shfl_down_sync(0xFFFFFFFFu, ns, o);
        rg += __shfl_down_sync(0xFFFFFFFFu, rg, o);
    }
    if (lane == 0) {
        out[warp]     = ps;
        out[B + warp] = ns;
        atomicAdd(&out[2 * B], rg * (1e-4f / (float)B));
    }
}

// ---------------------------------------------------------------------------
extern "C" void kernel_launch(void* const* d_in, const int* in_sizes, int n_in,
                              void* d_out, int out_size) {
    const float* ut    = (const float*)d_in[0];
    const float* it    = (const float*)d_in[1];
    const int*   eu    = (const int*)d_in[2];
    const int*   ei    = (const int*)d_in[3];
    const int*   users = (const int*)d_in[4];
    const int*   pos   = (const int*)d_in[5];
    const int*   neg   = (const int*)d_in[6];
    float*       out   = (float*)d_out;

    const int n_users = in_sizes[0] / EMB_D;
    const int n_items = in_sizes[1] / EMB_D;
    const int E       = in_sizes[2];
    const int B       = in_sizes[4];
    const int N       = n_users + n_items;

    void *p_degu, *p_degi, *p_cur;
    cudaGetSymbolAddress(&p_degu, g_degi_u);
    cudaGetSymbolAddress(&p_degi, g_degi_i);
    cudaGetSymbolAddress(&p_cur, g_cur);

    const int T = 256;

    // 1-2: degrees + weights
    cudaMemsetAsync(p_degu, 0, (size_t)n_users * sizeof(int), 0);
    cudaMemsetAsync(p_degi, 0, (size_t)n_items * sizeof(int), 0);
    deg_kernel<<<(E + T - 1) / T, T>>>(eu, ei, E);
    w_kernel<<<(E + T - 1) / T, T>>>(eu, ei, E);

    // 3: exclusive scan over N+1 degree entries -> g_off (off[N] = 2E)
    const int n_scan = N + 1;
    const int nb = (n_scan + SCAN_B - 1) / SCAN_B;
    scan1_kernel<<<nb, SCAN_B>>>(n_scan, n_users, N);
    scan2_kernel<<<1, SCAN_B>>>(nb);
    scan3_kernel<<<nb, SCAN_B>>>(n_scan);

    // 4: adjacency fill
    cudaMemsetAsync(p_cur, 0, (size_t)N * sizeof(int), 0);
    fill_kernel<<<(E + T - 1) / T, T>>>(eu, ei, E, n_users);

    // 5: two full propagation layers
    const int wpb = T / 32;
    const int gblocks = (N + wpb - 1) / wpb;
    gather1_kernel<<<gblocks, T>>>(ut, it, n_users, N);
    gather2_kernel<<<gblocks, T>>>(N);

    // 6: batch-sparse final layer + combine
    const int fblocks = (3 * B + wpb - 1) / wpb;
    final_kernel<<<fblocks, T>>>(ut, it, users, pos, neg, B, n_users);

    // 7: scoring
    cudaMemsetAsync(out + 2 * B, 0, sizeof(float), 0);
    score_kernel<<<(B * 32 + T - 1) / T, T>>>(ut, it, users, pos, neg, out, B);
}

// round 6
// speedup vs baseline: 2.9351x; 1.2338x over previous
#include <cuda_runtime.h>
#include <cuda_fp16.h>
#include <cstddef>

// LightGCN, CSR-gather, batch-sparse final layer, fp16 propagated storage.
// Per launch:
//   1. stacked degree histogram (int)
//   2. rs[i] = rsqrt(max(deg,1));  w(u,i) = rs[u]*rs[i] (exact factorization)
//   3. exclusive scan of degrees -> CSR offsets
//   4. fill packed adjacency (src id only, 4B) with atomic cursors
//   5. t16 = fp16(tables);  x1h = gather(t16);  x2h = gather(x1h)
//   6. fe[idx] = 0.25*(x0_fp32 + x1 + x2 + gather(x2h))  (batch rows only)
//   7. scoring from fe + L2 reg from fp32 tables
//
// NOTE: all device-global scratch is passed to kernels via pointers obtained
// with cudaGetSymbolAddress — never by referencing the symbol in host code.

#define NU_MAX 100000
#define NI_MAX 50000
#define N_MAX  (NU_MAX + NI_MAX)
#define E_MAX  1600000
#define B_MAX  4096
#define EMB_D  64
#define SCAN_B 1024

__device__ int     g_deg[N_MAX];
__device__ float   g_rs[N_MAX];
__device__ int     g_off[N_MAX + 1];
__device__ int     g_cur[N_MAX];
__device__ int     g_bsum[(N_MAX + SCAN_B) / SCAN_B + 2];
__device__ int     g_adj[(size_t)2 * E_MAX];
__device__ __half2 g_t16[(size_t)N_MAX * (EMB_D / 2)];
__device__ __half2 g_x1h[(size_t)N_MAX * (EMB_D / 2)];
__device__ __half2 g_x2h[(size_t)N_MAX * (EMB_D / 2)];
__device__ float   g_fe[(size_t)3 * B_MAX * EMB_D];

// ---------------------------------------------------------------------------
// 1. stacked degree histogram
__global__ void deg_kernel(const int* __restrict__ eu, const int* __restrict__ ei,
                           int E, int nu) {
    int e = blockIdx.x * blockDim.x + threadIdx.x;
    if (e < E) {
        atomicAdd(&g_deg[eu[e]], 1);
        atomicAdd(&g_deg[nu + ei[e]], 1);
    }
}

// 2. rs = rsqrt(max(deg,1))
__global__ void rs_kernel(int N) {
    int i = blockIdx.x * blockDim.x + threadIdx.x;
    if (i < N) g_rs[i] = rsqrtf(fmaxf((float)g_deg[i], 1.0f));
}

// 3a. per-block exclusive scan over n = N+1 entries (deg, padded with 0)
__global__ void scan1_kernel(int n, int N) {
    __shared__ int sh[SCAN_B];
    int tid = threadIdx.x;
    int i = blockIdx.x * SCAN_B + tid;
    int v = (i < N) ? g_deg[i] : 0;
    sh[tid] = v;
    __syncthreads();
    #pragma unroll
    for (int o = 1; o < SCAN_B; o <<= 1) {
        int t = (tid >= o) ? sh[tid - o] : 0;
        __syncthreads();
        sh[tid] += t;
        __syncthreads();
    }
    if (i < n) g_off[i] = sh[tid] - v;
    if (tid == SCAN_B - 1) g_bsum[blockIdx.x] = sh[tid];
}

__global__ void scan2_kernel(int nb) {
    __shared__ int sh[SCAN_B];
    int tid = threadIdx.x;
    int v = (tid < nb) ? g_bsum[tid] : 0;
    sh[tid] = v;
    __syncthreads();
    #pragma unroll
    for (int o = 1; o < SCAN_B; o <<= 1) {
        int t = (tid >= o) ? sh[tid - o] : 0;
        __syncthreads();
        sh[tid] += t;
        __syncthreads();
    }
    if (tid < nb) g_bsum[tid] = sh[tid] - v;
}

__global__ void scan3_kernel(int n) {
    int i = blockIdx.x * SCAN_B + threadIdx.x;
    if (i < n) g_off[i] += g_bsum[blockIdx.x];
}

// 4. fill packed adjacency (src ids only)
__global__ void fill_kernel(const int* __restrict__ eu, const int* __restrict__ ei,
                            int E, int nu) {
    int e = blockIdx.x * blockDim.x + threadIdx.x;
    if (e >= E) return;
    int u = eu[e];
    int r2 = nu + ei[e];
    int p1 = atomicAdd(&g_cur[u], 1);
    g_adj[(size_t)g_off[u] + p1] = r2;
    int p2 = atomicAdd(&g_cur[r2], 1);
    g_adj[(size_t)g_off[r2] + p2] = u;
}

// 5a. fp16 copy of stacked tables
__global__ void convert_kernel(const float2* __restrict__ ut, const float2* __restrict__ it,
                               int nu2, int ntot2) {
    int i = blockIdx.x * blockDim.x + threadIdx.x;
    if (i < ntot2) {
        float2 v = (i < nu2) ? ut[i] : it[i - nu2];
        g_t16[i] = __floats2half2_rn(v.x, v.y);
    }
}

// gather of fp16 rows with factorized weights; fp32 accumulation.
__device__ __forceinline__ float2 gather_row_h(const __half2* __restrict__ src,
                                               int node, int lane) {
    int beg = g_off[node];
    int end = g_off[node + 1];
    float sx = 0.0f, sy = 0.0f;
    int j = beg;
    for (; j + 3 < end; j += 4) {
        int c0 = __ldg(&g_adj[j]);
        int c1 = __ldg(&g_adj[j + 1]);
        int c2 = __ldg(&g_adj[j + 2]);
        int c3 = __ldg(&g_adj[j + 3]);
        float w0 = __ldg(&g_rs[c0]);
        float w1 = __ldg(&g_rs[c1]);
        float w2 = __ldg(&g_rs[c2]);
        float w3 = __ldg(&g_rs[c3]);
        float2 v0 = __half22float2(__ldg(src + (size_t)c0 * (EMB_D / 2) + lane));
        float2 v1 = __half22float2(__ldg(src + (size_t)c1 * (EMB_D / 2) + lane));
        float2 v2 = __half22float2(__ldg(src + (size_t)c2 * (EMB_D / 2) + lane));
        float2 v3 = __half22float2(__ldg(src + (size_t)c3 * (EMB_D / 2) + lane));
        sx += w0 * v0.x + w1 * v1.x + w2 * v2.x + w3 * v3.x;
        sy += w0 * v0.y + w1 * v1.y + w2 * v2.y + w3 * v3.y;
    }
    for (; j < end; ++j) {
        int c = __ldg(&g_adj[j]);
        float w = __ldg(&g_rs[c]);
        float2 v = __half22float2(__ldg(src + (size_t)c * (EMB_D / 2) + lane));
        sx += w * v.x;
        sy += w * v.y;
    }
    float rsd = g_rs[node];
    return make_float2(rsd * sx, rsd * sy);
}

// 5b. full-graph propagation layer: dst = gather(src), fp16 out
__global__ void gatherH_kernel(const __half2* __restrict__ src,
                               __half2* __restrict__ dst, int N) {
    int warp = (blockIdx.x * blockDim.x + threadIdx.x) >> 5;
    int lane = threadIdx.x & 31;
    if (warp >= N) return;
    float2 s = gather_row_h(src, warp, lane);
    dst[(size_t)warp * (EMB_D / 2) + lane] = __floats2half2_rn(s.x, s.y);
}

// 6. fe[idx] = 0.25*(x0 + x1 + x2 + gather(x2))  for the 3B batch rows
__global__ void final_kernel(const float* __restrict__ ut, const float* __restrict__ it,
                             const int* __restrict__ users, const int* __restrict__ pos,
                             const int* __restrict__ neg, int B, int nu) {
    int idx  = (blockIdx.x * blockDim.x + threadIdx.x) >> 5;
    int lane = threadIdx.x & 31;
    if (idx >= 3 * B) return;
    int node;
    if (idx < B)            node = users[idx];
    else if (idx < 2 * B)   node = nu + pos[idx - B];
    else                    node = nu + neg[idx - 2 * B];

    float2 x3 = gather_row_h(g_x2h, node, lane);

    const float* base0 = (node < nu) ? (ut + (size_t)node * EMB_D)
                                     : (it + (size_t)(node - nu) * EMB_D);
    float2 x0 = reinterpret_cast<const float2*>(base0)[lane];
    float2 x1 = __half22float2(g_x1h[(size_t)node * (EMB_D / 2) + lane]);
    float2 x2 = __half22float2(g_x2h[(size_t)node * (EMB_D / 2) + lane]);
    float2 f = make_float2(0.25f * (x0.x + x1.x + x2.x + x3.x),
                           0.25f * (x0.y + x1.y + x2.y + x3.y));
    reinterpret_cast<float2*>(g_fe + (size_t)idx * EMB_D)[lane] = f;
}

// 7. scoring: one warp per batch element
__global__ void score_kernel(const float* __restrict__ ut, const float* __restrict__ it,
                             const int* __restrict__ users, const int* __restrict__ pos,
                             const int* __restrict__ neg,
                             float* __restrict__ out, int B) {
    int warp = (blockIdx.x * blockDim.x + threadIdx.x) >> 5;
    int lane = threadIdx.x & 31;
    if (warp >= B) return;

    float2 vu = reinterpret_cast<const float2*>(g_fe + (size_t)warp * EMB_D)[lane];
    float2 vp = reinterpret_cast<const float2*>(g_fe + (size_t)(B + warp) * EMB_D)[lane];
    float2 vn = reinterpret_cast<const float2*>(g_fe + (size_t)(2 * B + warp) * EMB_D)[lane];
    float ps = vu.x * vp.x + vu.y * vp.y;
    float ns = vu.x * vn.x + vu.y * vn.y;

    int u = users[warp];
    int p = pos[warp];
    int n = neg[warp];
    float2 a = reinterpret_cast<const float2*>(ut + (size_t)u * EMB_D)[lane];
    float2 b = reinterpret_cast<const float2*>(it + (size_t)p * EMB_D)[lane];
    float2 c = reinterpret_cast<const float2*>(it + (size_t)n * EMB_D)[lane];
    float rg = a.x * a.x + a.y * a.y + b.x * b.x + b.y * b.y + c.x * c.x + c.y * c.y;

    #pragma unroll
    for (int o = 16; o > 0; o >>= 1) {
        ps += __shfl_down_sync(0xFFFFFFFFu, ps, o);
        ns += __shfl_down_sync(0xFFFFFFFFu, ns, o);
        rg += __shfl_down_sync(0xFFFFFFFFu, rg, o);
    }
    if (lane == 0) {
        out[warp]     = ps;
        out[B + warp] = ns;
        atomicAdd(&out[2 * B], rg * (1e-4f / (float)B));
    }
}

// ---------------------------------------------------------------------------
extern "C" void kernel_launch(void* const* d_in, const int* in_sizes, int n_in,
                              void* d_out, int out_size) {
    const float* ut    = (const float*)d_in[0];
    const float* it    = (const float*)d_in[1];
    const int*   eu    = (const int*)d_in[2];
    const int*   ei    = (const int*)d_in[3];
    const int*   users = (const int*)d_in[4];
    const int*   pos   = (const int*)d_in[5];
    const int*   neg   = (const int*)d_in[6];
    float*       out   = (float*)d_out;

    const int n_users = in_sizes[0] / EMB_D;
    const int n_items = in_sizes[1] / EMB_D;
    const int E       = in_sizes[2];
    const int B       = in_sizes[4];
    const int N       = n_users + n_items;

    void *p_deg, *p_cur, *p_t16, *p_x1h, *p_x2h;
    cudaGetSymbolAddress(&p_deg, g_deg);
    cudaGetSymbolAddress(&p_cur, g_cur);
    cudaGetSymbolAddress(&p_t16, g_t16);
    cudaGetSymbolAddress(&p_x1h, g_x1h);
    cudaGetSymbolAddress(&p_x2h, g_x2h);

    const int T = 256;

    // 5a (independent): fp16 table copy
    const int ntot2 = N * (EMB_D / 2);
    convert_kernel<<<(ntot2 + T - 1) / T, T>>>((const float2*)ut, (const float2*)it,
                                               n_users * (EMB_D / 2), ntot2);

    // 1-2: degrees + rs
    cudaMemsetAsync(p_deg, 0, (size_t)N * sizeof(int), 0);
    deg_kernel<<<(E + T - 1) / T, T>>>(eu, ei, E, n_users);
    rs_kernel<<<(N + T - 1) / T, T>>>(N);

    // 3: exclusive scan over N+1 entries -> g_off (off[N] = 2E)
    const int n_scan = N + 1;
    const int nb = (n_scan + SCAN_B - 1) / SCAN_B;
    scan1_kernel<<<nb, SCAN_B>>>(n_scan, N);
    scan2_kernel<<<1, SCAN_B>>>(nb);
    scan3_kernel<<<nb, SCAN_B>>>(n_scan);

    // 4: adjacency fill
    cudaMemsetAsync(p_cur, 0, (size_t)N * sizeof(int), 0);
    fill_kernel<<<(E + T - 1) / T, T>>>(eu, ei, E, n_users);

    // 5b: two full propagation layers (fp16 storage)
    const int wpb = T / 32;
    const int gblocks = (N + wpb - 1) / wpb;
    gatherH_kernel<<<gblocks, T>>>((const __half2*)p_t16, (__half2*)p_x1h, N);
    gatherH_kernel<<<gblocks, T>>>((const __half2*)p_x1h, (__half2*)p_x2h, N);

    // 6: batch-sparse final layer + combine
    const int fblocks = (3 * B + wpb - 1) / wpb;
    final_kernel<<<fblocks, T>>>(ut, it, users, pos, neg, B, n_users);

    // 7: scoring
    cudaMemsetAsync(out + 2 * B, 0, sizeof(float), 0);
    score_kernel<<<(B * 32 + T - 1) / T, T>>>(ut, it, users, pos, neg, out, B);
}